// round 11
// baseline (speedup 1.0000x reference)
#include <cuda_runtime.h>
#include <cuda_bf16.h>
#include <math.h>
#include <stdint.h>

#define N_NODES_MAX 50000
#define FEAT 128
#define OUTF 384
#define N_RBF 20

__device__ float g_phi[N_NODES_MAX * OUTF];

// B fragments for mma.m16n8k16, pre-packed per (ntile, ktile, lane):
//   b0 = {W[k0][n], W[k0+1][n]}, b1 = {W[k0+8][n], W[k0+9][n]}
//   k0 = 16*tk + 2*(lane%4), n = 8*tn + lane/4
__device__ uint2 g_w1f_hi[16 * 8 * 32], g_w1f_lo[16 * 8 * 32];
__device__ uint2 g_w2f_hi[48 * 8 * 32], g_w2f_lo[48 * 8 * 32];

// ---------------- f32x2 packed-math helpers (edge kernel) ----------------
__device__ __forceinline__ unsigned long long pack2(float lo, float hi) {
    unsigned long long r;
    asm("mov.b64 %0, {%1, %2};" : "=l"(r) : "f"(lo), "f"(hi));
    return r;
}
__device__ __forceinline__ unsigned long long dup2(float a) { return pack2(a, a); }
__device__ __forceinline__ void unpack2(unsigned long long v, float& lo, float& hi) {
    asm("mov.b64 {%0, %1}, %2;" : "=f"(lo), "=f"(hi) : "l"(v));
}
__device__ __forceinline__ unsigned long long fma2(unsigned long long a,
                                                   unsigned long long b,
                                                   unsigned long long c) {
    unsigned long long d;
    asm("fma.rn.f32x2 %0, %1, %2, %3;" : "=l"(d) : "l"(a), "l"(b), "l"(c));
    return d;
}
__device__ __forceinline__ unsigned long long mul2(unsigned long long a,
                                                   unsigned long long b) {
    unsigned long long d;
    asm("mul.rn.f32x2 %0, %1, %2;" : "=l"(d) : "l"(a), "l"(b));
    return d;
}

__device__ __forceinline__ uint32_t pk_bf2(__nv_bfloat16 a, __nv_bfloat16 b) {
    __nv_bfloat162 t = __halves2bfloat162(a, b);
    return *reinterpret_cast<uint32_t*>(&t);
}
__device__ __forceinline__ void split_bf(float v, __nv_bfloat16& h, __nv_bfloat16& l) {
    h = __float2bfloat16(v);
    l = __float2bfloat16(v - __bfloat162float(h));
}

// bf16 mma m16n8k16: D += A * B (fp32 accum)
__device__ __forceinline__ void mma16816(float* c, const uint32_t* a, uint2 b) {
    asm volatile(
        "mma.sync.aligned.m16n8k16.row.col.f32.bf16.bf16.f32 "
        "{%0,%1,%2,%3}, {%4,%5,%6,%7}, {%8,%9}, {%0,%1,%2,%3};"
        : "+f"(c[0]), "+f"(c[1]), "+f"(c[2]), "+f"(c[3])
        : "r"(a[0]), "r"(a[1]), "r"(a[2]), "r"(a[3]), "r"(b.x), "r"(b.y));
}

// ---------------------------------------------------------------------------
// Kernel 0: split W1/W2 into bf16 hi/lo B-fragments (lane-ordered).
// ---------------------------------------------------------------------------
__global__ void pack_weights_kernel(const float* __restrict__ W1,
                                    const float* __restrict__ W2)
{
    int idx = blockIdx.x * 256 + threadIdx.x;
    if (idx < 16 * 8 * 32) {            // W1: 16 ntiles x 8 ktiles x 32 lanes
        int l = idx & 31, t = idx >> 5;
        int tk = t & 7, tn = t >> 3;
        int k0 = tk * 16 + (l & 3) * 2;
        int n  = tn * 8 + (l >> 2);
        float v00 = W1[(k0)     * FEAT + n], v01 = W1[(k0 + 1) * FEAT + n];
        float v10 = W1[(k0 + 8) * FEAT + n], v11 = W1[(k0 + 9) * FEAT + n];
        __nv_bfloat16 h00, l00, h01, l01, h10, l10, h11, l11;
        split_bf(v00, h00, l00); split_bf(v01, h01, l01);
        split_bf(v10, h10, l10); split_bf(v11, h11, l11);
        g_w1f_hi[idx] = make_uint2(pk_bf2(h00, h01), pk_bf2(h10, h11));
        g_w1f_lo[idx] = make_uint2(pk_bf2(l00, l01), pk_bf2(l10, l11));
    }
    if (idx < 48 * 8 * 32) {            // W2: 48 ntiles x 8 ktiles x 32 lanes
        int l = idx & 31, t = idx >> 5;
        int tk = t & 7, tn = t >> 3;
        int k0 = tk * 16 + (l & 3) * 2;
        int n  = tn * 8 + (l >> 2);
        float v00 = W2[(k0)     * OUTF + n], v01 = W2[(k0 + 1) * OUTF + n];
        float v10 = W2[(k0 + 8) * OUTF + n], v11 = W2[(k0 + 9) * OUTF + n];
        __nv_bfloat16 h00, l00, h01, l01, h10, l10, h11, l11;
        split_bf(v00, h00, l00); split_bf(v01, h01, l01);
        split_bf(v10, h10, l10); split_bf(v11, h11, l11);
        g_w2f_hi[idx] = make_uint2(pk_bf2(h00, h01), pk_bf2(h10, h11));
        g_w2f_lo[idx] = make_uint2(pk_bf2(l00, l01), pk_bf2(l10, l11));
    }
}

// ---------------------------------------------------------------------------
// Kernel A: node MLP via mma.sync bf16 3-term split.
//   Block = 128 rows, 256 threads (8 warps); warp owns 16 rows.
//   A (s, then h) staged in smem bf16 hi/lo, row-major, LDA_BF=136 (no-conflict).
// ---------------------------------------------------------------------------
constexpr int LDA_BF = 136;
constexpr int NODE_SMEM = 128 * LDA_BF * 2 * 2;   // hi+lo, bf16 -> 69632 B

__global__ __launch_bounds__(256)
void node_mma_kernel(const float* __restrict__ s,
                     const float* __restrict__ b1,
                     const float* __restrict__ b2,
                     int n_nodes)
{
    extern __shared__ __nv_bfloat16 smA[];
    __nv_bfloat16* Ahi = smA;
    __nv_bfloat16* Alo = smA + 128 * LDA_BF;

    const int tid  = threadIdx.x;
    const int warp = tid >> 5, lane = tid & 31;
    const int grp  = lane >> 2, qid = lane & 3;
    const int row0 = blockIdx.x * 128;
    const int wr0  = warp * 16;

    // ---- stage s -> bf16 hi/lo split ----
    for (int i = tid; i < 128 * 16; i += 256) {
        int r = i >> 4, kc = (i & 15) << 3;
        int gr = row0 + r;
        float vv[8];
        if (gr < n_nodes) {
            float4 a0 = *(const float4*)&s[(size_t)gr * FEAT + kc];
            float4 a1 = *(const float4*)&s[(size_t)gr * FEAT + kc + 4];
            vv[0] = a0.x; vv[1] = a0.y; vv[2] = a0.z; vv[3] = a0.w;
            vv[4] = a1.x; vv[5] = a1.y; vv[6] = a1.z; vv[7] = a1.w;
        } else {
#pragma unroll
            for (int j = 0; j < 8; j++) vv[j] = 0.f;
        }
        uint32_t ph[4], pl[4];
#pragma unroll
        for (int j = 0; j < 4; j++) {
            __nv_bfloat16 h0, l0, h1, l1;
            split_bf(vv[2 * j], h0, l0);
            split_bf(vv[2 * j + 1], h1, l1);
            ph[j] = pk_bf2(h0, h1);
            pl[j] = pk_bf2(l0, l1);
        }
        *(uint4*)&Ahi[r * LDA_BF + kc] = make_uint4(ph[0], ph[1], ph[2], ph[3]);
        *(uint4*)&Alo[r * LDA_BF + kc] = make_uint4(pl[0], pl[1], pl[2], pl[3]);
    }
    __syncthreads();

    // ---- GEMM1: D1 = s @ W1 (3-term) ----
    float acc[16][4];
#pragma unroll
    for (int t = 0; t < 16; t++)
#pragma unroll
        for (int j = 0; j < 4; j++) acc[t][j] = 0.f;

#pragma unroll
    for (int tk = 0; tk < 8; tk++) {
        int k0 = tk * 16 + qid * 2;
        uint32_t ahi[4], alo[4];
        ahi[0] = *(const uint32_t*)&Ahi[(wr0 + grp)     * LDA_BF + k0];
        ahi[1] = *(const uint32_t*)&Ahi[(wr0 + grp + 8) * LDA_BF + k0];
        ahi[2] = *(const uint32_t*)&Ahi[(wr0 + grp)     * LDA_BF + k0 + 8];
        ahi[3] = *(const uint32_t*)&Ahi[(wr0 + grp + 8) * LDA_BF + k0 + 8];
        alo[0] = *(const uint32_t*)&Alo[(wr0 + grp)     * LDA_BF + k0];
        alo[1] = *(const uint32_t*)&Alo[(wr0 + grp + 8) * LDA_BF + k0];
        alo[2] = *(const uint32_t*)&Alo[(wr0 + grp)     * LDA_BF + k0 + 8];
        alo[3] = *(const uint32_t*)&Alo[(wr0 + grp + 8) * LDA_BF + k0 + 8];
#pragma unroll
        for (int tn = 0; tn < 16; tn++) {
            uint2 bh = __ldg(&g_w1f_hi[(tn * 8 + tk) * 32 + lane]);
            uint2 bl = __ldg(&g_w1f_lo[(tn * 8 + tk) * 32 + lane]);
            mma16816(acc[tn], ahi, bh);
            mma16816(acc[tn], ahi, bl);
            mma16816(acc[tn], alo, bh);
        }
    }

    // ---- epilogue1: h = silu(D1 + b1), split -> back into A (warp-private rows)
#pragma unroll
    for (int tn = 0; tn < 16; tn++) {
        int c0 = tn * 8 + qid * 2;
        float2 bb = __ldg((const float2*)&b1[c0]);
        float x0 = acc[tn][0] + bb.x, x1 = acc[tn][1] + bb.y;   // row grp
        float x2 = acc[tn][2] + bb.x, x3 = acc[tn][3] + bb.y;   // row grp+8
        float h0 = x0 * __frcp_rn(1.0f + __expf(-x0));
        float h1 = x1 * __frcp_rn(1.0f + __expf(-x1));
        float h2 = x2 * __frcp_rn(1.0f + __expf(-x2));
        float h3 = x3 * __frcp_rn(1.0f + __expf(-x3));
        __nv_bfloat16 hh0, ll0, hh1, ll1, hh2, ll2, hh3, ll3;
        split_bf(h0, hh0, ll0); split_bf(h1, hh1, ll1);
        split_bf(h2, hh2, ll2); split_bf(h3, hh3, ll3);
        *(uint32_t*)&Ahi[(wr0 + grp)     * LDA_BF + c0] = pk_bf2(hh0, hh1);
        *(uint32_t*)&Ahi[(wr0 + grp + 8) * LDA_BF + c0] = pk_bf2(hh2, hh3);
        *(uint32_t*)&Alo[(wr0 + grp)     * LDA_BF + c0] = pk_bf2(ll0, ll1);
        *(uint32_t*)&Alo[(wr0 + grp + 8) * LDA_BF + c0] = pk_bf2(ll2, ll3);
    }
    // no __syncthreads: A rows are warp-private from here on

    // ---- GEMM2: phi = h @ W2 (+b2), 3 chunks of N=128 ----
    for (int ch = 0; ch < 3; ch++) {
        float acc2[16][4];
#pragma unroll
        for (int t = 0; t < 16; t++)
#pragma unroll
            for (int j = 0; j < 4; j++) acc2[t][j] = 0.f;

#pragma unroll
        for (int tk = 0; tk < 8; tk++) {
            int k0 = tk * 16 + qid * 2;
            uint32_t ahi[4], alo[4];
            ahi[0] = *(const uint32_t*)&Ahi[(wr0 + grp)     * LDA_BF + k0];
            ahi[1] = *(const uint32_t*)&Ahi[(wr0 + grp + 8) * LDA_BF + k0];
            ahi[2] = *(const uint32_t*)&Ahi[(wr0 + grp)     * LDA_BF + k0 + 8];
            ahi[3] = *(const uint32_t*)&Ahi[(wr0 + grp + 8) * LDA_BF + k0 + 8];
            alo[0] = *(const uint32_t*)&Alo[(wr0 + grp)     * LDA_BF + k0];
            alo[1] = *(const uint32_t*)&Alo[(wr0 + grp + 8) * LDA_BF + k0];
            alo[2] = *(const uint32_t*)&Alo[(wr0 + grp)     * LDA_BF + k0 + 8];
            alo[3] = *(const uint32_t*)&Alo[(wr0 + grp + 8) * LDA_BF + k0 + 8];
#pragma unroll
            for (int tn = 0; tn < 16; tn++) {
                int gtn = ch * 16 + tn;
                uint2 bh = __ldg(&g_w2f_hi[(gtn * 8 + tk) * 32 + lane]);
                uint2 bl = __ldg(&g_w2f_lo[(gtn * 8 + tk) * 32 + lane]);
                mma16816(acc2[tn], ahi, bh);
                mma16816(acc2[tn], ahi, bl);
                mma16816(acc2[tn], alo, bh);
            }
        }

        // epilogue: + b2, store to g_phi
        int r1 = row0 + wr0 + grp;
        int r2 = r1 + 8;
#pragma unroll
        for (int tn = 0; tn < 16; tn++) {
            int col = ch * 128 + tn * 8 + qid * 2;
            float2 bb = __ldg((const float2*)&b2[col]);
            if (r1 < n_nodes)
                *(float2*)&g_phi[(size_t)r1 * OUTF + col] =
                    make_float2(acc2[tn][0] + bb.x, acc2[tn][1] + bb.y);
            if (r2 < n_nodes)
                *(float2*)&g_phi[(size_t)r2 * OUTF + col] =
                    make_float2(acc2[tn][2] + bb.x, acc2[tn][3] + bb.y);
        }
    }
}

// ---------------------------------------------------------------------------
// Kernel B: fused edge kernel (UNCHANGED from R6 — 263us measured).
// ---------------------------------------------------------------------------
constexpr int EPB = 32;

__global__ __launch_bounds__(256, 3)
void edge_kernel(const float* __restrict__ dist,
                 const int* __restrict__ nbrs,
                 const float* __restrict__ Wd, const float* __restrict__ bd,
                 float* __restrict__ out, int n_edges, int n_nodes)
{
    __shared__ float srbf[N_RBF][EPB];
    __shared__ float senv[EPB];
    __shared__ int   sj[EPB];

    const int tid = threadIdx.x;
    const int e0  = blockIdx.x * EPB;

    if (tid < EPB) {
        int e = e0 + tid;
        float d = (e < n_edges) ? dist[e] : 1.0f;
        float th = d * 0.62831853071795864769f;
        float sn, cs;
        sincosf(th, &sn, &cs);
        float inv = (d == 0.0f) ? 0.0f : (1.0f / d);
        float env = (d < 5.0f) ? (0.5f * (cs + 1.0f)) : 0.0f;
        float scale = env * inv;
        senv[tid] = env;
        int j = (e < n_edges) ? nbrs[2 * e + 1] : 0;
        j = (j < 0) ? 0 : ((j >= n_nodes) ? (n_nodes - 1) : j);
        sj[tid] = j;

        float sm1 = sn, sm0 = 0.0f;
        float twoc = 2.0f * cs;
        srbf[0][tid] = sn * scale;
#pragma unroll
        for (int n = 1; n < N_RBF; n++) {
            float snn = fmaf(twoc, sm1, -sm0);
            sm0 = sm1; sm1 = snn;
            srbf[n][tid] = snn * scale;
        }
    }
    __syncthreads();

    const int warp = tid >> 5;
    const int lane = tid & 31;
    const int c0 = blockIdx.y * 128 + lane * 4;
    const int eb = warp * 4;

    float4 ph[4];
#pragma unroll
    for (int i = 0; i < 4; i++)
        ph[i] = __ldg((const float4*)&g_phi[(size_t)sj[eb + i] * OUTF + c0]);

    const ulonglong2 bd2 = __ldg((const ulonglong2*)&bd[c0]);
    unsigned long long acc[4][2];
#pragma unroll
    for (int i = 0; i < 4; i++) {
        unsigned long long env2 = dup2(senv[eb + i]);
        acc[i][0] = mul2(env2, bd2.x);
        acc[i][1] = mul2(env2, bd2.y);
    }

#pragma unroll
    for (int n = 0; n < N_RBF; n++) {
        ulonglong2 wd2 = __ldg((const ulonglong2*)&Wd[n * OUTF + c0]);
        float4 r = *(const float4*)&srbf[n][eb];
        unsigned long long rd0 = dup2(r.x), rd1 = dup2(r.y),
                           rd2 = dup2(r.z), rd3 = dup2(r.w);
        acc[0][0] = fma2(rd0, wd2.x, acc[0][0]);
        acc[0][1] = fma2(rd0, wd2.y, acc[0][1]);
        acc[1][0] = fma2(rd1, wd2.x, acc[1][0]);
        acc[1][1] = fma2(rd1, wd2.y, acc[1][1]);
        acc[2][0] = fma2(rd2, wd2.x, acc[2][0]);
        acc[2][1] = fma2(rd2, wd2.y, acc[2][1]);
        acc[3][0] = fma2(rd3, wd2.x, acc[3][0]);
        acc[3][1] = fma2(rd3, wd2.y, acc[3][1]);
    }

#pragma unroll
    for (int i = 0; i < 4; i++) {
        int e = e0 + eb + i;
        if (e >= n_edges) continue;
        float w0, w1, w2, w3;
        unpack2(acc[i][0], w0, w1);
        unpack2(acc[i][1], w2, w3);
        float4 o = make_float4(ph[i].x * w0, ph[i].y * w1,
                               ph[i].z * w2, ph[i].w * w3);
        *(float4*)&out[(size_t)e * OUTF + c0] = o;
    }
}

// ---------------------------------------------------------------------------
extern "C" void kernel_launch(void* const* d_in, const int* in_sizes, int n_in,
                              void* d_out, int out_size)
{
    const float* s    = (const float*)d_in[0];
    const float* dist = (const float*)d_in[1];
    const int*   nbrs = (const int*)d_in[2];     // int32
    const float* W1   = (const float*)d_in[3];
    const float* b1   = (const float*)d_in[4];
    const float* W2   = (const float*)d_in[5];
    const float* b2   = (const float*)d_in[6];
    const float* Wd   = (const float*)d_in[7];
    const float* bd   = (const float*)d_in[8];
    float* out = (float*)d_out;

    const int n_nodes = in_sizes[0] / FEAT;
    const int n_edges = in_sizes[1];

    pack_weights_kernel<<<(48 * 8 * 32 + 255) / 256, 256>>>(W1, W2);

    cudaFuncSetAttribute(node_mma_kernel,
                         cudaFuncAttributeMaxDynamicSharedMemorySize,
                         NODE_SMEM);
    int node_blocks = (n_nodes + 127) / 128;
    node_mma_kernel<<<node_blocks, 256, NODE_SMEM>>>(s, b1, b2, n_nodes);

    dim3 egrid((n_edges + EPB - 1) / EPB, 3);
    edge_kernel<<<egrid, 256>>>(dist, nbrs, Wd, bd, out, n_edges, n_nodes);
}

// round 12
// speedup vs baseline: 1.0035x; 1.0035x over previous
#include <cuda_runtime.h>
#include <cuda_bf16.h>
#include <math.h>
#include <stdint.h>

#define N_NODES_MAX 50000
#define FEAT 128
#define OUTF 384
#define N_RBF 20

__device__ float g_phi[N_NODES_MAX * OUTF];

// B fragments for mma.m16n8k16, pre-packed per (ntile, ktile, lane):
//   b0 = {W[k0][n], W[k0+1][n]}, b1 = {W[k0+8][n], W[k0+9][n]}
//   k0 = 16*tk + 2*(lane%4), n = 8*tn + lane/4
__device__ uint2 g_w1f_hi[16 * 8 * 32], g_w1f_lo[16 * 8 * 32];
__device__ uint2 g_w2f_hi[48 * 8 * 32], g_w2f_lo[48 * 8 * 32];

// ---------------- f32x2 packed-math helpers (edge kernel) ----------------
__device__ __forceinline__ unsigned long long pack2(float lo, float hi) {
    unsigned long long r;
    asm("mov.b64 %0, {%1, %2};" : "=l"(r) : "f"(lo), "f"(hi));
    return r;
}
__device__ __forceinline__ unsigned long long dup2(float a) { return pack2(a, a); }
__device__ __forceinline__ void unpack2(unsigned long long v, float& lo, float& hi) {
    asm("mov.b64 {%0, %1}, %2;" : "=f"(lo), "=f"(hi) : "l"(v));
}
__device__ __forceinline__ unsigned long long fma2(unsigned long long a,
                                                   unsigned long long b,
                                                   unsigned long long c) {
    unsigned long long d;
    asm("fma.rn.f32x2 %0, %1, %2, %3;" : "=l"(d) : "l"(a), "l"(b), "l"(c));
    return d;
}
__device__ __forceinline__ unsigned long long mul2(unsigned long long a,
                                                   unsigned long long b) {
    unsigned long long d;
    asm("mul.rn.f32x2 %0, %1, %2;" : "=l"(d) : "l"(a), "l"(b));
    return d;
}

__device__ __forceinline__ uint32_t pk_bf2(__nv_bfloat16 a, __nv_bfloat16 b) {
    __nv_bfloat162 t = __halves2bfloat162(a, b);
    return *reinterpret_cast<uint32_t*>(&t);
}
__device__ __forceinline__ void split_bf(float v, __nv_bfloat16& h, __nv_bfloat16& l) {
    h = __float2bfloat16(v);
    l = __float2bfloat16(v - __bfloat162float(h));
}

// bf16 mma m16n8k16: D += A * B (fp32 accum)
__device__ __forceinline__ void mma16816(float* c, const uint32_t* a, uint2 b) {
    asm volatile(
        "mma.sync.aligned.m16n8k16.row.col.f32.bf16.bf16.f32 "
        "{%0,%1,%2,%3}, {%4,%5,%6,%7}, {%8,%9}, {%0,%1,%2,%3};"
        : "+f"(c[0]), "+f"(c[1]), "+f"(c[2]), "+f"(c[3])
        : "r"(a[0]), "r"(a[1]), "r"(a[2]), "r"(a[3]), "r"(b.x), "r"(b.y));
}

// ---------------------------------------------------------------------------
// Kernel 0: split W1/W2 into bf16 hi/lo B-fragments (lane-ordered).
// ---------------------------------------------------------------------------
__global__ void pack_weights_kernel(const float* __restrict__ W1,
                                    const float* __restrict__ W2)
{
    int idx = blockIdx.x * 256 + threadIdx.x;
    if (idx < 16 * 8 * 32) {            // W1: 16 ntiles x 8 ktiles x 32 lanes
        int l = idx & 31, t = idx >> 5;
        int tk = t & 7, tn = t >> 3;
        int k0 = tk * 16 + (l & 3) * 2;
        int n  = tn * 8 + (l >> 2);
        float v00 = W1[(k0)     * FEAT + n], v01 = W1[(k0 + 1) * FEAT + n];
        float v10 = W1[(k0 + 8) * FEAT + n], v11 = W1[(k0 + 9) * FEAT + n];
        __nv_bfloat16 h00, l00, h01, l01, h10, l10, h11, l11;
        split_bf(v00, h00, l00); split_bf(v01, h01, l01);
        split_bf(v10, h10, l10); split_bf(v11, h11, l11);
        g_w1f_hi[idx] = make_uint2(pk_bf2(h00, h01), pk_bf2(h10, h11));
        g_w1f_lo[idx] = make_uint2(pk_bf2(l00, l01), pk_bf2(l10, l11));
    }
    if (idx < 48 * 8 * 32) {            // W2: 48 ntiles x 8 ktiles x 32 lanes
        int l = idx & 31, t = idx >> 5;
        int tk = t & 7, tn = t >> 3;
        int k0 = tk * 16 + (l & 3) * 2;
        int n  = tn * 8 + (l >> 2);
        float v00 = W2[(k0)     * OUTF + n], v01 = W2[(k0 + 1) * OUTF + n];
        float v10 = W2[(k0 + 8) * OUTF + n], v11 = W2[(k0 + 9) * OUTF + n];
        __nv_bfloat16 h00, l00, h01, l01, h10, l10, h11, l11;
        split_bf(v00, h00, l00); split_bf(v01, h01, l01);
        split_bf(v10, h10, l10); split_bf(v11, h11, l11);
        g_w2f_hi[idx] = make_uint2(pk_bf2(h00, h01), pk_bf2(h10, h11));
        g_w2f_lo[idx] = make_uint2(pk_bf2(l00, l01), pk_bf2(l10, l11));
    }
}

// ---------------------------------------------------------------------------
// Kernel A: node MLP via mma.sync bf16 3-term split.
//   Block = 128 rows, 256 threads (8 warps); warp owns 16 rows.
//   A (s, then h) staged in smem bf16 hi/lo, row-major, LDA_BF=136 (no-conflict).
// ---------------------------------------------------------------------------
constexpr int LDA_BF = 136;
constexpr int NODE_SMEM = 128 * LDA_BF * 2 * 2;   // hi+lo, bf16 -> 69632 B

__global__ __launch_bounds__(256)
void node_mma_kernel(const float* __restrict__ s,
                     const float* __restrict__ b1,
                     const float* __restrict__ b2,
                     int n_nodes)
{
    extern __shared__ __nv_bfloat16 smA[];
    __nv_bfloat16* Ahi = smA;
    __nv_bfloat16* Alo = smA + 128 * LDA_BF;

    const int tid  = threadIdx.x;
    const int warp = tid >> 5, lane = tid & 31;
    const int grp  = lane >> 2, qid = lane & 3;
    const int row0 = blockIdx.x * 128;
    const int wr0  = warp * 16;

    // ---- stage s -> bf16 hi/lo split ----
    for (int i = tid; i < 128 * 16; i += 256) {
        int r = i >> 4, kc = (i & 15) << 3;
        int gr = row0 + r;
        float vv[8];
        if (gr < n_nodes) {
            float4 a0 = *(const float4*)&s[(size_t)gr * FEAT + kc];
            float4 a1 = *(const float4*)&s[(size_t)gr * FEAT + kc + 4];
            vv[0] = a0.x; vv[1] = a0.y; vv[2] = a0.z; vv[3] = a0.w;
            vv[4] = a1.x; vv[5] = a1.y; vv[6] = a1.z; vv[7] = a1.w;
        } else {
#pragma unroll
            for (int j = 0; j < 8; j++) vv[j] = 0.f;
        }
        uint32_t ph[4], pl[4];
#pragma unroll
        for (int j = 0; j < 4; j++) {
            __nv_bfloat16 h0, l0, h1, l1;
            split_bf(vv[2 * j], h0, l0);
            split_bf(vv[2 * j + 1], h1, l1);
            ph[j] = pk_bf2(h0, h1);
            pl[j] = pk_bf2(l0, l1);
        }
        *(uint4*)&Ahi[r * LDA_BF + kc] = make_uint4(ph[0], ph[1], ph[2], ph[3]);
        *(uint4*)&Alo[r * LDA_BF + kc] = make_uint4(pl[0], pl[1], pl[2], pl[3]);
    }
    __syncthreads();

    // ---- GEMM1: D1 = s @ W1 (3-term) ----
    float acc[16][4];
#pragma unroll
    for (int t = 0; t < 16; t++)
#pragma unroll
        for (int j = 0; j < 4; j++) acc[t][j] = 0.f;

#pragma unroll
    for (int tk = 0; tk < 8; tk++) {
        int k0 = tk * 16 + qid * 2;
        uint32_t ahi[4], alo[4];
        ahi[0] = *(const uint32_t*)&Ahi[(wr0 + grp)     * LDA_BF + k0];
        ahi[1] = *(const uint32_t*)&Ahi[(wr0 + grp + 8) * LDA_BF + k0];
        ahi[2] = *(const uint32_t*)&Ahi[(wr0 + grp)     * LDA_BF + k0 + 8];
        ahi[3] = *(const uint32_t*)&Ahi[(wr0 + grp + 8) * LDA_BF + k0 + 8];
        alo[0] = *(const uint32_t*)&Alo[(wr0 + grp)     * LDA_BF + k0];
        alo[1] = *(const uint32_t*)&Alo[(wr0 + grp + 8) * LDA_BF + k0];
        alo[2] = *(const uint32_t*)&Alo[(wr0 + grp)     * LDA_BF + k0 + 8];
        alo[3] = *(const uint32_t*)&Alo[(wr0 + grp + 8) * LDA_BF + k0 + 8];
#pragma unroll
        for (int tn = 0; tn < 16; tn++) {
            uint2 bh = __ldg(&g_w1f_hi[(tn * 8 + tk) * 32 + lane]);
            uint2 bl = __ldg(&g_w1f_lo[(tn * 8 + tk) * 32 + lane]);
            mma16816(acc[tn], ahi, bh);
            mma16816(acc[tn], ahi, bl);
            mma16816(acc[tn], alo, bh);
        }
    }

    // ---- epilogue1: h = silu(D1 + b1), split -> back into A (warp-private rows)
#pragma unroll
    for (int tn = 0; tn < 16; tn++) {
        int c0 = tn * 8 + qid * 2;
        float2 bb = __ldg((const float2*)&b1[c0]);
        float x0 = acc[tn][0] + bb.x, x1 = acc[tn][1] + bb.y;   // row grp
        float x2 = acc[tn][2] + bb.x, x3 = acc[tn][3] + bb.y;   // row grp+8
        float h0 = x0 * __frcp_rn(1.0f + __expf(-x0));
        float h1 = x1 * __frcp_rn(1.0f + __expf(-x1));
        float h2 = x2 * __frcp_rn(1.0f + __expf(-x2));
        float h3 = x3 * __frcp_rn(1.0f + __expf(-x3));
        __nv_bfloat16 hh0, ll0, hh1, ll1, hh2, ll2, hh3, ll3;
        split_bf(h0, hh0, ll0); split_bf(h1, hh1, ll1);
        split_bf(h2, hh2, ll2); split_bf(h3, hh3, ll3);
        *(uint32_t*)&Ahi[(wr0 + grp)     * LDA_BF + c0] = pk_bf2(hh0, hh1);
        *(uint32_t*)&Ahi[(wr0 + grp + 8) * LDA_BF + c0] = pk_bf2(hh2, hh3);
        *(uint32_t*)&Alo[(wr0 + grp)     * LDA_BF + c0] = pk_bf2(ll0, ll1);
        *(uint32_t*)&Alo[(wr0 + grp + 8) * LDA_BF + c0] = pk_bf2(ll2, ll3);
    }
    // no __syncthreads: A rows are warp-private from here on

    // ---- GEMM2: phi = h @ W2 (+b2), 3 chunks of N=128 ----
    for (int ch = 0; ch < 3; ch++) {
        float acc2[16][4];
#pragma unroll
        for (int t = 0; t < 16; t++)
#pragma unroll
            for (int j = 0; j < 4; j++) acc2[t][j] = 0.f;

#pragma unroll
        for (int tk = 0; tk < 8; tk++) {
            int k0 = tk * 16 + qid * 2;
            uint32_t ahi[4], alo[4];
            ahi[0] = *(const uint32_t*)&Ahi[(wr0 + grp)     * LDA_BF + k0];
            ahi[1] = *(const uint32_t*)&Ahi[(wr0 + grp + 8) * LDA_BF + k0];
            ahi[2] = *(const uint32_t*)&Ahi[(wr0 + grp)     * LDA_BF + k0 + 8];
            ahi[3] = *(const uint32_t*)&Ahi[(wr0 + grp + 8) * LDA_BF + k0 + 8];
            alo[0] = *(const uint32_t*)&Alo[(wr0 + grp)     * LDA_BF + k0];
            alo[1] = *(const uint32_t*)&Alo[(wr0 + grp + 8) * LDA_BF + k0];
            alo[2] = *(const uint32_t*)&Alo[(wr0 + grp)     * LDA_BF + k0 + 8];
            alo[3] = *(const uint32_t*)&Alo[(wr0 + grp + 8) * LDA_BF + k0 + 8];
#pragma unroll
            for (int tn = 0; tn < 16; tn++) {
                int gtn = ch * 16 + tn;
                uint2 bh = __ldg(&g_w2f_hi[(gtn * 8 + tk) * 32 + lane]);
                uint2 bl = __ldg(&g_w2f_lo[(gtn * 8 + tk) * 32 + lane]);
                mma16816(acc2[tn], ahi, bh);
                mma16816(acc2[tn], ahi, bl);
                mma16816(acc2[tn], alo, bh);
            }
        }

        // epilogue: + b2, store to g_phi
        int r1 = row0 + wr0 + grp;
        int r2 = r1 + 8;
#pragma unroll
        for (int tn = 0; tn < 16; tn++) {
            int col = ch * 128 + tn * 8 + qid * 2;
            float2 bb = __ldg((const float2*)&b2[col]);
            if (r1 < n_nodes)
                *(float2*)&g_phi[(size_t)r1 * OUTF + col] =
                    make_float2(acc2[tn][0] + bb.x, acc2[tn][1] + bb.y);
            if (r2 < n_nodes)
                *(float2*)&g_phi[(size_t)r2 * OUTF + col] =
                    make_float2(acc2[tn][2] + bb.x, acc2[tn][3] + bb.y);
        }
    }
}

// ---------------------------------------------------------------------------
// Kernel B: fused edge kernel (UNCHANGED from R6 — 263us measured).
// ---------------------------------------------------------------------------
constexpr int EPB = 32;

__global__ __launch_bounds__(256, 3)
void edge_kernel(const float* __restrict__ dist,
                 const int* __restrict__ nbrs,
                 const float* __restrict__ Wd, const float* __restrict__ bd,
                 float* __restrict__ out, int n_edges, int n_nodes)
{
    __shared__ float srbf[N_RBF][EPB];
    __shared__ float senv[EPB];
    __shared__ int   sj[EPB];

    const int tid = threadIdx.x;
    const int e0  = blockIdx.x * EPB;

    if (tid < EPB) {
        int e = e0 + tid;
        float d = (e < n_edges) ? dist[e] : 1.0f;
        float th = d * 0.62831853071795864769f;
        float sn, cs;
        sincosf(th, &sn, &cs);
        float inv = (d == 0.0f) ? 0.0f : (1.0f / d);
        float env = (d < 5.0f) ? (0.5f * (cs + 1.0f)) : 0.0f;
        float scale = env * inv;
        senv[tid] = env;
        int j = (e < n_edges) ? nbrs[2 * e + 1] : 0;
        j = (j < 0) ? 0 : ((j >= n_nodes) ? (n_nodes - 1) : j);
        sj[tid] = j;

        float sm1 = sn, sm0 = 0.0f;
        float twoc = 2.0f * cs;
        srbf[0][tid] = sn * scale;
#pragma unroll
        for (int n = 1; n < N_RBF; n++) {
            float snn = fmaf(twoc, sm1, -sm0);
            sm0 = sm1; sm1 = snn;
            srbf[n][tid] = snn * scale;
        }
    }
    __syncthreads();

    const int warp = tid >> 5;
    const int lane = tid & 31;
    const int c0 = blockIdx.y * 128 + lane * 4;
    const int eb = warp * 4;

    float4 ph[4];
#pragma unroll
    for (int i = 0; i < 4; i++)
        ph[i] = __ldg((const float4*)&g_phi[(size_t)sj[eb + i] * OUTF + c0]);

    const ulonglong2 bd2 = __ldg((const ulonglong2*)&bd[c0]);
    unsigned long long acc[4][2];
#pragma unroll
    for (int i = 0; i < 4; i++) {
        unsigned long long env2 = dup2(senv[eb + i]);
        acc[i][0] = mul2(env2, bd2.x);
        acc[i][1] = mul2(env2, bd2.y);
    }

#pragma unroll
    for (int n = 0; n < N_RBF; n++) {
        ulonglong2 wd2 = __ldg((const ulonglong2*)&Wd[n * OUTF + c0]);
        float4 r = *(const float4*)&srbf[n][eb];
        unsigned long long rd0 = dup2(r.x), rd1 = dup2(r.y),
                           rd2 = dup2(r.z), rd3 = dup2(r.w);
        acc[0][0] = fma2(rd0, wd2.x, acc[0][0]);
        acc[0][1] = fma2(rd0, wd2.y, acc[0][1]);
        acc[1][0] = fma2(rd1, wd2.x, acc[1][0]);
        acc[1][1] = fma2(rd1, wd2.y, acc[1][1]);
        acc[2][0] = fma2(rd2, wd2.x, acc[2][0]);
        acc[2][1] = fma2(rd2, wd2.y, acc[2][1]);
        acc[3][0] = fma2(rd3, wd2.x, acc[3][0]);
        acc[3][1] = fma2(rd3, wd2.y, acc[3][1]);
    }

#pragma unroll
    for (int i = 0; i < 4; i++) {
        int e = e0 + eb + i;
        if (e >= n_edges) continue;
        float w0, w1, w2, w3;
        unpack2(acc[i][0], w0, w1);
        unpack2(acc[i][1], w2, w3);
        float4 o = make_float4(ph[i].x * w0, ph[i].y * w1,
                               ph[i].z * w2, ph[i].w * w3);
        *(float4*)&out[(size_t)e * OUTF + c0] = o;
    }
}

// ---------------------------------------------------------------------------
extern "C" void kernel_launch(void* const* d_in, const int* in_sizes, int n_in,
                              void* d_out, int out_size)
{
    const float* s    = (const float*)d_in[0];
    const float* dist = (const float*)d_in[1];
    const int*   nbrs = (const int*)d_in[2];     // int32
    const float* W1   = (const float*)d_in[3];
    const float* b1   = (const float*)d_in[4];
    const float* W2   = (const float*)d_in[5];
    const float* b2   = (const float*)d_in[6];
    const float* Wd   = (const float*)d_in[7];
    const float* bd   = (const float*)d_in[8];
    float* out = (float*)d_out;

    const int n_nodes = in_sizes[0] / FEAT;
    const int n_edges = in_sizes[1];

    pack_weights_kernel<<<(48 * 8 * 32 + 255) / 256, 256>>>(W1, W2);

    cudaFuncSetAttribute(node_mma_kernel,
                         cudaFuncAttributeMaxDynamicSharedMemorySize,
                         NODE_SMEM);
    int node_blocks = (n_nodes + 127) / 128;
    node_mma_kernel<<<node_blocks, 256, NODE_SMEM>>>(s, b1, b2, n_nodes);

    dim3 egrid((n_edges + EPB - 1) / EPB, 3);
    edge_kernel<<<egrid, 256>>>(dist, nbrs, Wd, bd, out, n_edges, n_nodes);
}